// round 7
// baseline (speedup 1.0000x reference)
#include <cuda_runtime.h>

#define NBATCH 8
#define NPTS   8192
#define NS     512
#define NK     32
#define DM     128
#define NHEAD  8
#define HDIM   16
#define NLAY   4
#define DFF    256
#define DOUT   256
#define NGROUP (NBATCH*NS)
#define EPSV   1e-5f

// ---------------- scratch (device globals; no allocation allowed) ----------------
__device__ float g_featT[NBATCH*NPTS*DM];       // [B,N,D]
__device__ float g_newxyz[NBATCH*NS*3];         // centers
__device__ float g_fcout[NBATCH*DOUT*NS];       // fc output [B,O,S]
__device__ float g_wqkv_t[NLAY*DM*384];
__device__ float g_wo_t[NLAY*DM*DM];
__device__ float g_w1_t[NLAY*DM*DFF];
__device__ float g_w2_t[NLAY*DFF*DM];
__device__ float g_fc_t[DM*DOUT];
__device__ float g_pe2_t[64*DM];

// ---------------- packed f32x2 helpers ----------------
__device__ __forceinline__ unsigned long long pk2(float x){
    unsigned long long r;
    asm("mov.b64 %0, {%1, %1};" : "=l"(r) : "r"(__float_as_uint(x)));
    return r;
}
__device__ __forceinline__ unsigned long long pack2(float lo, float hi){
    unsigned long long r;
    asm("mov.b64 %0, {%1, %2};" : "=l"(r) : "r"(__float_as_uint(lo)), "r"(__float_as_uint(hi)));
    return r;
}
__device__ __forceinline__ unsigned long long fma2(unsigned long long a, unsigned long long b, unsigned long long c){
    unsigned long long d;
    asm("fma.rn.f32x2 %0, %1, %2, %3;" : "=l"(d) : "l"(a), "l"(b), "l"(c));
    return d;
}
__device__ __forceinline__ unsigned long long add2(unsigned long long a, unsigned long long b){
    unsigned long long d;
    asm("add.rn.f32x2 %0, %1, %2;" : "=l"(d) : "l"(a), "l"(b));
    return d;
}
__device__ __forceinline__ unsigned long long mul2(unsigned long long a, unsigned long long b){
    unsigned long long d;
    asm("mul.rn.f32x2 %0, %1, %2;" : "=l"(d) : "l"(a), "l"(b));
    return d;
}
__device__ __forceinline__ float2 up2(unsigned long long a){
    float2 f; unsigned lo, hi;
    asm("mov.b64 {%0, %1}, %2;" : "=r"(lo), "=r"(hi) : "l"(a));
    f.x = __uint_as_float(lo); f.y = __uint_as_float(hi);
    return f;
}

// ---------------- fused weight-prep kernels ----------------
__global__ void k_prep1(const float* __restrict__ wqkv, const float* __restrict__ wo){
    int i0 = blockIdx.x*256 + threadIdx.x;
    int stride = gridDim.x*256;
    for (int idx=i0; idx<NLAY*384*128; idx+=stride){
        int L = idx/(384*128), r = idx - L*384*128;
        int m = r>>7, k = r&127;
        g_wqkv_t[L*384*128 + k*384 + m] = wqkv[idx];
    }
    for (int idx=i0; idx<NLAY*128*128; idx+=stride){
        int L = idx/(128*128), r = idx - L*128*128;
        int m = r>>7, k = r&127;
        g_wo_t[L*128*128 + k*128 + m] = wo[idx];
    }
}
__global__ void k_prep2(const float* __restrict__ w1, const float* __restrict__ w2,
                        const float* __restrict__ fc, const float* __restrict__ pe2){
    int i0 = blockIdx.x*256 + threadIdx.x;
    int stride = gridDim.x*256;
    for (int idx=i0; idx<NLAY*256*128; idx+=stride){
        int L = idx/(256*128), r = idx - L*256*128;
        int m = r>>7, k = r&127;
        g_w1_t[L*256*128 + k*256 + m] = w1[idx];
    }
    for (int idx=i0; idx<NLAY*128*256; idx+=stride){
        int L = idx/(128*256), r = idx - L*128*256;
        int m = r>>8, k = r&255;
        g_w2_t[L*128*256 + k*128 + m] = w2[idx];
    }
    for (int idx=i0; idx<256*128; idx+=stride){
        int m = idx>>7, k = idx&127;
        g_fc_t[k*256 + m] = fc[idx];
    }
    for (int idx=i0; idx<128*64; idx+=stride){
        int m = idx>>6, k = idx&63;
        g_pe2_t[k*128 + m] = pe2[idx];
    }
}

// ---------------- features [B,D,N] -> [B,N,D] ----------------
__global__ void k_featT(const float* __restrict__ f){
    __shared__ float tile[32][33];
    int b = blockIdx.z;
    int n0 = blockIdx.x*32, d0 = blockIdx.y*32;
    int tx = threadIdx.x, ty = threadIdx.y;
    for (int j = ty; j < 32; j += 8)
        tile[j][tx] = f[((size_t)b*DM + d0 + j)*NPTS + n0 + tx];
    __syncthreads();
    for (int j = ty; j < 32; j += 8)
        g_featT[((size_t)b*NPTS + n0 + j)*DM + d0 + tx] = tile[tx][j];
}

// ---------------- farthest point sampling: packed f32x2 distance math ----------------
__global__ __launch_bounds__(512) void k_fps(const float* __restrict__ xyz, float* __restrict__ out0){
    int b = blockIdx.x, tid = threadIdx.x;
    const float* X = xyz + (size_t)b*3*NPTS;
    // pairs: q holds points (tid+2q*512, tid+(2q+1)*512) in (lo,hi)
    unsigned long long px2[8], py2[8], pz2[8];
    float dist[16];
#pragma unroll
    for (int q=0;q<8;q++){
        int i0 = tid + (2*q)*512, i1 = tid + (2*q+1)*512;
        px2[q] = pack2(X[i0],          X[i1]);
        py2[q] = pack2(X[NPTS+i0],     X[NPTS+i1]);
        pz2[q] = pack2(X[2*NPTS+i0],   X[2*NPTS+i1]);
        dist[2*q] = 1e10f; dist[2*q+1] = 1e10f;
    }
    __shared__ float s_c[3];
    __shared__ float s_v[16]; __shared__ int s_i[16];
    int far = 0;
    int lane = tid & 31, warp = tid >> 5;
    for (int it=0; it<NS; it++){
        if (tid == (far & 511)){
            int j = far >> 9;
            float2 tx = up2(px2[j>>1]), ty = up2(py2[j>>1]), tz = up2(pz2[j>>1]);
            float vx = (j&1) ? tx.y : tx.x;
            float vy = (j&1) ? ty.y : ty.x;
            float vz = (j&1) ? tz.y : tz.x;
            s_c[0]=vx; s_c[1]=vy; s_c[2]=vz;
            float* nx = g_newxyz + ((size_t)b*NS + it)*3;
            nx[0]=vx; nx[1]=vy; nx[2]=vz;
            out0[(size_t)b*3*NS + it]        = vx;
            out0[(size_t)b*3*NS + NS + it]   = vy;
            out0[(size_t)b*3*NS + 2*NS + it] = vz;
        }
        __syncthreads();
        float cx=s_c[0], cy=s_c[1], cz=s_c[2];
        unsigned long long ncx = pk2(-cx), ncy = pk2(-cy), ncz = pk2(-cz);
        float bv=-1.0f; int bi=0x7fffffff;
#pragma unroll
        for (int q=0;q<8;q++){
            // per-element identical rounding to __fadd_rn/__fmul_rn chain
            unsigned long long dx = add2(px2[q], ncx);
            unsigned long long dy = add2(py2[q], ncy);
            unsigned long long dz = add2(pz2[q], ncz);
            unsigned long long s  = add2(mul2(dx,dx), mul2(dy,dy));
            unsigned long long d  = add2(s, mul2(dz,dz));
            float2 df = up2(d);
            float nd0 = fminf(dist[2*q],   df.x); dist[2*q]   = nd0;
            if (nd0 > bv){ bv = nd0; bi = tid + (2*q)*512; }
            float nd1 = fminf(dist[2*q+1], df.y); dist[2*q+1] = nd1;
            if (nd1 > bv){ bv = nd1; bi = tid + (2*q+1)*512; }
        }
#pragma unroll
        for (int off=16; off; off>>=1){
            float ov = __shfl_down_sync(0xffffffffu, bv, off);
            int   oi = __shfl_down_sync(0xffffffffu, bi, off);
            if (ov > bv || (ov == bv && oi < bi)){ bv=ov; bi=oi; }
        }
        if (lane==0){ s_v[warp]=bv; s_i[warp]=bi; }
        __syncthreads();
        float gv = s_v[lane & 15]; int gi = s_i[lane & 15];
#pragma unroll
        for (int off=8; off; off>>=1){
            float ov = __shfl_xor_sync(0xffffffffu, gv, off);
            int   oi = __shfl_xor_sync(0xffffffffu, gi, off);
            if (ov > gv || (ov == gv && oi < gi)){ gv=ov; gi=oi; }
        }
        far = gi;
    }
}

// ---------------- GEMM tile, weights staged through smem, float4 x loads ----------------
template<int NJ4, int KC, bool RELU>
__device__ __forceinline__ void gemm_smem(const float* src, int sld, int K,
    const float* __restrict__ Wt, const float* __restrict__ bias,
    float* ws, float* dst, int dld, int warp, int lane, int tid)
{
    const int M = 128*NJ4;
    const float* s0 = src + warp*4*sld;
    unsigned long long acc[4][2*NJ4];
#pragma unroll
    for (int i=0;i<4;i++)
#pragma unroll
        for (int j=0;j<2*NJ4;j++) acc[i][j]=0ull;

    for (int k0=0; k0<K; k0+=KC){
        __syncthreads();
        {   // cooperative stage: KC*M floats
            const float4* gs = (const float4*)(Wt + (size_t)k0*M);
            float4* sd = (float4*)ws;
            const int n4 = KC*M/4;
#pragma unroll
            for (int i=tid; i<n4; i+=256) sd[i] = gs[i];
        }
        __syncthreads();
#pragma unroll
        for (int kk4=0; kk4<KC/4; kk4++){
            float xa0[4], xa1[4], xa2[4], xa3[4];
            *(float4*)xa0 = *(const float4*)(s0 +           k0 + kk4*4);
            *(float4*)xa1 = *(const float4*)(s0 +   sld +   k0 + kk4*4);
            *(float4*)xa2 = *(const float4*)(s0 + 2*sld +   k0 + kk4*4);
            *(float4*)xa3 = *(const float4*)(s0 + 3*sld +   k0 + kk4*4);
#pragma unroll
            for (int q=0;q<4;q++){
                unsigned long long X0=pk2(xa0[q]), X1=pk2(xa1[q]), X2=pk2(xa2[q]), X3=pk2(xa3[q]);
                const ulonglong2* w = (const ulonglong2*)(ws + (kk4*4+q)*M) + lane;
#pragma unroll
                for (int j=0;j<NJ4;j++){
                    ulonglong2 wv = w[32*j];
                    acc[0][2*j]   = fma2(X0, wv.x, acc[0][2*j]);
                    acc[1][2*j]   = fma2(X1, wv.x, acc[1][2*j]);
                    acc[2][2*j]   = fma2(X2, wv.x, acc[2][2*j]);
                    acc[3][2*j]   = fma2(X3, wv.x, acc[3][2*j]);
                    acc[0][2*j+1] = fma2(X0, wv.y, acc[0][2*j+1]);
                    acc[1][2*j+1] = fma2(X1, wv.y, acc[1][2*j+1]);
                    acc[2][2*j+1] = fma2(X2, wv.y, acc[2][2*j+1]);
                    acc[3][2*j+1] = fma2(X3, wv.y, acc[3][2*j+1]);
                }
            }
        }
    }
#pragma unroll
    for (int j=0;j<NJ4;j++){
        float4 bv = *(const float4*)(bias + 4*lane + 128*j);
#pragma unroll
        for (int i=0;i<4;i++){
            float2 a0 = up2(acc[i][2*j]), a1 = up2(acc[i][2*j+1]);
            float4 v;
            v.x = a0.x + bv.x; v.y = a0.y + bv.y; v.z = a1.x + bv.z; v.w = a1.y + bv.w;
            if (RELU){ v.x=fmaxf(v.x,0.f); v.y=fmaxf(v.y,0.f); v.z=fmaxf(v.z,0.f); v.w=fmaxf(v.w,0.f); }
            *(float4*)(dst + (warp*4+i)*dld + 4*lane + 128*j) = v;
        }
    }
}

__device__ __forceinline__ void add_ln(float* xs, const float* y,
    const float* __restrict__ gam, const float* __restrict__ bet, int tid)
{
    int t = tid>>3, sub = tid&7;
    float* xr = xs + t*136 + sub*16;
    const float* yr = y + t*388 + sub*16;
    float v[16]; float s=0.0f;
#pragma unroll
    for (int d=0; d<16; d++){ v[d] = xr[d] + yr[d]; s += v[d]; }
#pragma unroll
    for (int m=4;m;m>>=1) s += __shfl_xor_sync(0xffffffffu, s, m, 8);
    float mean = s * (1.0f/128.0f);
    float s2=0.0f;
#pragma unroll
    for (int d=0;d<16;d++){ float dv = v[d]-mean; s2 += dv*dv; }
#pragma unroll
    for (int m=4;m;m>>=1) s2 += __shfl_xor_sync(0xffffffffu, s2, m, 8);
    float rs = 1.0f / sqrtf(s2*(1.0f/128.0f) + EPSV);
#pragma unroll
    for (int d=0;d<16;d++){
        int dd = sub*16 + d;
        xr[d] = (v[d]-mean)*rs*gam[dd] + bet[dd];
    }
}

// smem: xs 32x136 | bf 32x388 | ws 6144 floats (weight staging; knn arrays overlap here)
#define SMEM_FLOATS (32*136 + 32*388 + 6144)

__global__ __launch_bounds__(256,2) void k_xform(
    const float* __restrict__ xyz,
    const float* __restrict__ pe_w1, const float* __restrict__ pe_b1,
    const float* __restrict__ bn_g,  const float* __restrict__ bn_b,
    const float* __restrict__ bn_m,  const float* __restrict__ bn_v,
    const float* __restrict__ pe_b2,
    const float* __restrict__ bqkv, const float* __restrict__ bo,
    const float* __restrict__ l1g,  const float* __restrict__ l1b,
    const float* __restrict__ b1,   const float* __restrict__ b2,
    const float* __restrict__ l2g,  const float* __restrict__ l2b,
    const float* __restrict__ fcb)
{
    extern __shared__ float sm[];
    float* xs = sm;                    // 32 x 136
    float* bf = sm + 32*136;           // 32 x 388
    float* ws = sm + 32*136 + 32*388;  // weight staging / knn scratch
    int g = blockIdx.x, tid = threadIdx.x;
    int warp = tid>>5, lane = tid&31;
    int b = g >> 9;

    // ===== Phase 1: kNN + positional encoding (scratch in ws region) =====
    {
        int*   sel  = (int*)ws;          // 32
        float* gxp  = ws + 32;           // 32*3
        float* hbuf = ws + 128;          // 32*64
        float* svv  = ws + 128 + 2048;   // 8
        int*   sii  = (int*)(ws + 128 + 2048 + 8); // 8
        const float* X = xyz + (size_t)b*3*NPTS;
        const float* c = g_newxyz + (size_t)g*3;
        float cx=c[0], cy=c[1], cz=c[2];
        float cn2 = __fadd_rn(__fadd_rn(__fmul_rn(cx,cx),__fmul_rn(cy,cy)),__fmul_rn(cz,cz));
        float v[32];
        float bv=3.4e38f; int bi=0x7fffffff;
#pragma unroll
        for (int j=0;j<32;j++){
            int i = tid + j*256;
            float x=X[i], y=X[NPTS+i], z=X[2*NPTS+i];
            float pn2 = __fadd_rn(__fadd_rn(__fmul_rn(x,x),__fmul_rn(y,y)),__fmul_rn(z,z));
            float dot = __fadd_rn(__fadd_rn(__fmul_rn(cx,x),__fmul_rn(cy,y)),__fmul_rn(cz,z));
            float d = __fadd_rn(__fadd_rn(cn2,pn2), __fmul_rn(-2.0f,dot));
            v[j] = d;
            if (d < bv){ bv=d; bi=i; }
        }
        unsigned removed = 0u;
        for (int r=0;r<NK;r++){
            float wv=bv; int wi=bi;
#pragma unroll
            for (int off=16; off; off>>=1){
                float ov=__shfl_down_sync(0xffffffffu,wv,off);
                int   oi=__shfl_down_sync(0xffffffffu,wi,off);
                if (ov<wv || (ov==wv && oi<wi)){wv=ov;wi=oi;}
            }
            if (lane==0){ svv[warp]=wv; sii[warp]=wi; }
            __syncthreads();
            float gv = svv[lane & 7]; int gi = sii[lane & 7];
#pragma unroll
            for (int off=4; off; off>>=1){
                float ov=__shfl_xor_sync(0xffffffffu,gv,off);
                int   oi=__shfl_xor_sync(0xffffffffu,gi,off);
                if (ov<gv || (ov==gv && oi<gi)){gv=ov;gi=oi;}
            }
            if (tid==0) sel[r]=gi;
            __syncthreads();   // protect svv reuse next round
            if ((gi & 255) == tid){
                removed |= 1u << (gi >> 8);
                bv=3.4e38f; bi=0x7fffffff;
#pragma unroll
                for (int j=0;j<32;j++){
                    if (!((removed>>j)&1u) && v[j] < bv){ bv=v[j]; bi=tid+j*256; }
                }
            }
        }
        if (tid < 96){
            int k = tid/3, cc = tid - k*3;
            gxp[k*3+cc] = X[cc*NPTS + sel[k]];
        }
        __syncthreads();
        for (int e=tid;e<NK*64;e+=256){
            int k=e>>6, cc=e&63;
            float val = pe_b1[cc] + gxp[k*3]*pe_w1[cc*3] + gxp[k*3+1]*pe_w1[cc*3+1] + gxp[k*3+2]*pe_w1[cc*3+2];
            val = (val - bn_m[cc]) / sqrtf(bn_v[cc] + EPSV) * bn_g[cc] + bn_b[cc];
            hbuf[k*64+cc] = fmaxf(val, 0.0f);
        }
        __syncthreads();
        {
            int k = tid >> 3, dl = tid & 7;
            float acc[16];
#pragma unroll
            for (int jj=0;jj<16;jj++) acc[jj] = pe_b2[dl + 8*jj];
            for (int cc=0;cc<64;cc++){
                float hv = hbuf[k*64+cc];
                const float* w = g_pe2_t + cc*DM + dl;
#pragma unroll
                for (int jj=0;jj<16;jj++) acc[jj] += hv * __ldg(w + 8*jj);
            }
            const float* fr = g_featT + ((size_t)b*NPTS + sel[k])*DM + dl;
            float* xo = xs + k*136 + dl;
#pragma unroll
            for (int jj=0;jj<16;jj++) xo[8*jj] = fr[8*jj] + acc[jj];
        }
    }
    __syncthreads();

    // ===== Phase 2: 4 transformer layers =====
    for (int L=0;L<NLAY;L++){
        gemm_smem<3,16,false>(xs,136,128, g_wqkv_t + L*DM*384, bqkv + L*384, ws, bf,388, warp,lane,tid);
        __syncthreads();
        {
            int qo = warp*HDIM, ko = 128 + warp*HDIM, vo = 256 + warp*HDIM;
            float* row = bf + lane*388;
            const ulonglong2* qr = (const ulonglong2*)(row+qo);
            ulonglong2 qa = qr[0], qb = qr[1], qc = qr[2], qd = qr[3];
            float s[32];
#pragma unroll 4
            for (int j=0;j<32;j++){
                const ulonglong2* kr = (const ulonglong2*)(bf + j*388 + ko);
                ulonglong2 ka = kr[0], kb = kr[1], kc = kr[2], kd = kr[3];
                unsigned long long p = 0ull;
                p = fma2(qa.x, ka.x, p); p = fma2(qa.y, ka.y, p);
                p = fma2(qb.x, kb.x, p); p = fma2(qb.y, kb.y, p);
                p = fma2(qc.x, kc.x, p); p = fma2(qc.y, kc.y, p);
                p = fma2(qd.x, kd.x, p); p = fma2(qd.y, kd.y, p);
                float2 pf = up2(p);
                s[j] = (pf.x + pf.y) * 0.25f;
            }
            float mx=-3.4e38f;
#pragma unroll
            for (int j=0;j<32;j++) mx = fmaxf(mx, s[j]);
            float sum=0.0f;
#pragma unroll
            for (int j=0;j<32;j++){ s[j]=__expf(s[j]-mx); sum+=s[j]; }
            float inv = 1.0f/sum;
            unsigned long long o[8];
#pragma unroll
            for (int m=0;m<8;m++) o[m]=0ull;
#pragma unroll 4
            for (int j=0;j<32;j++){
                unsigned long long P = pk2(s[j]*inv);
                const ulonglong2* vr = (const ulonglong2*)(bf + j*388 + vo);
                ulonglong2 va = vr[0], vb = vr[1], vc = vr[2], vd = vr[3];
                o[0]=fma2(P,va.x,o[0]); o[1]=fma2(P,va.y,o[1]);
                o[2]=fma2(P,vb.x,o[2]); o[3]=fma2(P,vb.y,o[3]);
                o[4]=fma2(P,vc.x,o[4]); o[5]=fma2(P,vc.y,o[5]);
                o[6]=fma2(P,vd.x,o[6]); o[7]=fma2(P,vd.y,o[7]);
            }
            ulonglong2* orow = (ulonglong2*)(row+qo);
            orow[0] = make_ulonglong2(o[0],o[1]);
            orow[1] = make_ulonglong2(o[2],o[3]);
            orow[2] = make_ulonglong2(o[4],o[5]);
            orow[3] = make_ulonglong2(o[6],o[7]);
        }
        __syncthreads();
        gemm_smem<1,32,false>(bf,388,128, g_wo_t + L*DM*DM, bo + L*DM, ws, bf+256,388, warp,lane,tid);
        __syncthreads();
        add_ln(xs, bf+256, l1g + L*DM, l1b + L*DM, tid);
        __syncthreads();
        gemm_smem<2,16,true>(xs,136,128, g_w1_t + L*DM*DFF, b1 + L*DFF, ws, bf,388, warp,lane,tid);
        __syncthreads();
        gemm_smem<1,32,false>(bf,388,256, g_w2_t + L*DFF*DM, b2 + L*DM, ws, bf+256,388, warp,lane,tid);
        __syncthreads();
        add_ln(xs, bf+256, l2g + L*DM, l2b + L*DM, tid);
        __syncthreads();
    }
    // max pool over tokens
    if (tid < DM){
        float m = -3.4e38f;
#pragma unroll
        for (int t=0;t<NK;t++) m = fmaxf(m, xs[t*136+tid]);
        bf[tid] = m;
    }
    __syncthreads();
    // FC: 256 outputs
    {
        int o = tid;
        float acc = fcb[o];
#pragma unroll 4
        for (int k=0;k<DM;k++) acc += bf[k]*__ldg(g_fc_t + k*DOUT + o);
        int bb = g>>9, s = g & 511;
        g_fcout[((size_t)bb*DOUT + o)*NS + s] = acc;
    }
}

// ---------------- linear upsample [B,O,S] -> [B,O,N] ----------------
__global__ void k_interp(float* __restrict__ out){
    int i = blockIdx.x*256 + threadIdx.x;
    if (i >= NBATCH*DOUT*NPTS) return;
    int n = i & (NPTS-1);
    int rest = i >> 13;   // b*256 + o
    float pos = (float)n * (511.0f/8191.0f);
    float fi = floorf(pos);
    int i0 = (int)fi;
    int i1 = min(i0+1, NS-1);
    float w = pos - fi;
    const float* row = g_fcout + (size_t)rest*NS;
    out[NBATCH*3*NS + i] = row[i0]*(1.0f-w) + row[i1]*w;
}

// ---------------- launch ----------------
extern "C" void kernel_launch(void* const* d_in, const int* in_sizes, int n_in,
                              void* d_out, int out_size)
{
    (void)in_sizes; (void)n_in; (void)out_size;
    const float* xyz   = (const float*)d_in[0];
    const float* feat  = (const float*)d_in[1];
    const float* pe_w1 = (const float*)d_in[2];
    const float* pe_b1 = (const float*)d_in[3];
    const float* bn_g  = (const float*)d_in[4];
    const float* bn_b  = (const float*)d_in[5];
    const float* bn_m  = (const float*)d_in[6];
    const float* bn_v  = (const float*)d_in[7];
    const float* pe_w2 = (const float*)d_in[8];
    const float* pe_b2 = (const float*)d_in[9];
    const float* wqkv  = (const float*)d_in[10];
    const float* bqkv  = (const float*)d_in[11];
    const float* wo    = (const float*)d_in[12];
    const float* bo    = (const float*)d_in[13];
    const float* l1g   = (const float*)d_in[14];
    const float* l1b   = (const float*)d_in[15];
    const float* w1    = (const float*)d_in[16];
    const float* b1    = (const float*)d_in[17];
    const float* w2    = (const float*)d_in[18];
    const float* b2    = (const float*)d_in[19];
    const float* l2g   = (const float*)d_in[20];
    const float* l2b   = (const float*)d_in[21];
    const float* fcw   = (const float*)d_in[22];
    const float* fcb   = (const float*)d_in[23];
    float* out = (float*)d_out;

    k_prep1<<<256,256>>>(wqkv, wo);
    k_prep2<<<256,256>>>(w1, w2, fcw, pe_w2);
    k_featT<<<dim3(NPTS/32, DM/32, NBATCH), dim3(32,8)>>>(feat);
    k_fps<<<NBATCH,512>>>(xyz, out);
    cudaFuncSetAttribute(k_xform, cudaFuncAttributeMaxDynamicSharedMemorySize, SMEM_FLOATS*4);
    k_xform<<<NGROUP,256,SMEM_FLOATS*4>>>(xyz, pe_w1, pe_b1, bn_g, bn_b, bn_m, bn_v, pe_b2,
                                          bqkv,bo,l1g,l1b,b1,b2,l2g,l2b,fcb);
    k_interp<<<(NBATCH*DOUT*NPTS)/256,256>>>(out);
}

// round 12
// speedup vs baseline: 1.7158x; 1.7158x over previous
#include <cuda_runtime.h>

#define NBATCH 8
#define NPTS   8192
#define NS     512
#define NK     32
#define DM     128
#define NHEAD  8
#define HDIM   16
#define NLAY   4
#define DFF    256
#define DOUT   256
#define NGROUP (NBATCH*NS)
#define EPSV   1e-5f

// ---------------- scratch (device globals; no allocation allowed) ----------------
__device__ float g_featT[NBATCH*NPTS*DM];       // [B,N,D]
__device__ float g_newxyz[NBATCH*NS*3];         // centers
__device__ float g_xbuf[(size_t)NGROUP*NK*DM];  // tokens
__device__ float g_fcout[NBATCH*DOUT*NS];       // fc output [B,O,S]
__device__ float g_wqkv_t[NLAY*DM*384];
__device__ float g_wo_t[NLAY*DM*DM];
__device__ float g_w1_t[NLAY*DM*DFF];
__device__ float g_w2_t[NLAY*DFF*DM];
__device__ float g_fc_t[DM*DOUT];
__device__ float g_pe2_t[64*DM];

// ---------------- packed f32x2 helpers ----------------
__device__ __forceinline__ unsigned long long pk2(float x){
    unsigned long long r;
    asm("mov.b64 %0, {%1, %1};" : "=l"(r) : "r"(__float_as_uint(x)));
    return r;
}
__device__ __forceinline__ unsigned long long fma2(unsigned long long a, unsigned long long b, unsigned long long c){
    unsigned long long d;
    asm("fma.rn.f32x2 %0, %1, %2, %3;" : "=l"(d) : "l"(a), "l"(b), "l"(c));
    return d;
}
__device__ __forceinline__ float2 up2(unsigned long long a){
    float2 f; unsigned lo, hi;
    asm("mov.b64 {%0, %1}, %2;" : "=r"(lo), "=r"(hi) : "l"(a));
    f.x = __uint_as_float(lo); f.y = __uint_as_float(hi);
    return f;
}
// ---------------- cp.async helpers ----------------
__device__ __forceinline__ void cpasync16(float4* smem_dst, const float4* gsrc){
    unsigned s = (unsigned)__cvta_generic_to_shared(smem_dst);
    asm volatile("cp.async.cg.shared.global [%0], [%1], 16;" :: "r"(s), "l"(gsrc));
}
#define CPASYNC_COMMIT asm volatile("cp.async.commit_group;")
#define CPASYNC_WAIT0  asm volatile("cp.async.wait_group 0;")

// ---------------- fused prep: weight transposes + feature transpose ----------------
// blocks [0,8192): featT 32x32 tiles; blocks [8192,8704): weight transposes
__global__ __launch_bounds__(256) void k_prep(
    const float* __restrict__ f,
    const float* __restrict__ wqkv, const float* __restrict__ wo,
    const float* __restrict__ w1,   const float* __restrict__ w2,
    const float* __restrict__ fc,   const float* __restrict__ pe2)
{
    __shared__ float tile[32][33];
    int blk = blockIdx.x, tid = threadIdx.x;
    if (blk < 8192){
        int n0 = (blk & 255)*32, d0 = ((blk>>8)&3)*32, b = blk>>10;
        int tx = tid & 31, ty = tid >> 5;
        for (int j = ty; j < 32; j += 8)
            tile[j][tx] = f[((size_t)b*DM + d0 + j)*NPTS + n0 + tx];
        __syncthreads();
        for (int j = ty; j < 32; j += 8)
            g_featT[((size_t)b*NPTS + n0 + j)*DM + d0 + tx] = tile[tx][j];
        return;
    }
    int i0 = (blk-8192)*256 + tid;
    const int stride = 512*256;
    for (int idx=i0; idx<NLAY*384*128; idx+=stride){
        int L = idx/(384*128), r = idx - L*384*128;
        int m = r>>7, k = r&127;
        g_wqkv_t[L*384*128 + k*384 + m] = wqkv[idx];
    }
    for (int idx=i0; idx<NLAY*128*128; idx+=stride){
        int L = idx/(128*128), r = idx - L*128*128;
        int m = r>>7, k = r&127;
        g_wo_t[L*128*128 + k*128 + m] = wo[idx];
    }
    for (int idx=i0; idx<NLAY*256*128; idx+=stride){
        int L = idx/(256*128), r = idx - L*256*128;
        int m = r>>7, k = r&127;
        g_w1_t[L*256*128 + k*256 + m] = w1[idx];
    }
    for (int idx=i0; idx<NLAY*128*256; idx+=stride){
        int L = idx/(128*256), r = idx - L*128*256;
        int m = r>>8, k = r&255;
        g_w2_t[L*128*256 + k*128 + m] = w2[idx];
    }
    for (int idx=i0; idx<256*128; idx+=stride){
        int m = idx>>7, k = idx&127;
        g_fc_t[k*256 + m] = fc[idx];
    }
    for (int idx=i0; idx<128*64; idx+=stride){
        int m = idx>>6, k = idx&63;
        g_pe2_t[k*128 + m] = pe2[idx];
    }
}

// ---------------- farthest point sampling: 512 thr/block, 2 barriers/iter (R6 version) ----------------
__global__ __launch_bounds__(512) void k_fps(const float* __restrict__ xyz, float* __restrict__ out0){
    int b = blockIdx.x, tid = threadIdx.x;
    const float* X = xyz + (size_t)b*3*NPTS;
    float px[16], py[16], pz[16], dist[16];
#pragma unroll
    for (int j=0;j<16;j++){
        int i = tid + j*512;
        px[j]=X[i]; py[j]=X[NPTS+i]; pz[j]=X[2*NPTS+i]; dist[j]=1e10f;
    }
    __shared__ float s_c[3];
    __shared__ float s_v[16]; __shared__ int s_i[16];
    int far = 0;
    int lane = tid & 31, warp = tid >> 5;
    for (int it=0; it<NS; it++){
        if (tid == (far & 511)){
            int j = far >> 9;
            s_c[0]=px[j]; s_c[1]=py[j]; s_c[2]=pz[j];
            float* nx = g_newxyz + ((size_t)b*NS + it)*3;
            nx[0]=px[j]; nx[1]=py[j]; nx[2]=pz[j];
            out0[(size_t)b*3*NS + it]        = px[j];
            out0[(size_t)b*3*NS + NS + it]   = py[j];
            out0[(size_t)b*3*NS + 2*NS + it] = pz[j];
        }
        __syncthreads();
        float cx=s_c[0], cy=s_c[1], cz=s_c[2];
        float bv=-1.0f; int bi=0x7fffffff;
#pragma unroll
        for (int j=0;j<16;j++){
            float dx=__fadd_rn(px[j],-cx), dy=__fadd_rn(py[j],-cy), dz=__fadd_rn(pz[j],-cz);
            float d = __fadd_rn(__fadd_rn(__fmul_rn(dx,dx),__fmul_rn(dy,dy)),__fmul_rn(dz,dz));
            float nd = fminf(dist[j], d);
            dist[j] = nd;
            if (nd > bv){ bv = nd; bi = tid + j*512; }
        }
#pragma unroll
        for (int off=16; off; off>>=1){
            float ov = __shfl_down_sync(0xffffffffu, bv, off);
            int   oi = __shfl_down_sync(0xffffffffu, bi, off);
            if (ov > bv || (ov == bv && oi < bi)){ bv=ov; bi=oi; }
        }
        if (lane==0){ s_v[warp]=bv; s_i[warp]=bi; }
        __syncthreads();
        float gv = s_v[lane & 15]; int gi = s_i[lane & 15];
#pragma unroll
        for (int off=8; off; off>>=1){
            float ov = __shfl_xor_sync(0xffffffffu, gv, off);
            int   oi = __shfl_xor_sync(0xffffffffu, gi, off);
            if (ov > gv || (ov == gv && oi < gi)){ gv=ov; gi=oi; }
        }
        far = gi;
    }
}

// ---------------- kNN + PE (standalone, high occupancy; R6 version) ----------------
__global__ __launch_bounds__(256) void k_knn_pe(
    const float* __restrict__ xyz,
    const float* __restrict__ pe_w1, const float* __restrict__ pe_b1,
    const float* __restrict__ bn_g,  const float* __restrict__ bn_b,
    const float* __restrict__ bn_m,  const float* __restrict__ bn_v,
    const float* __restrict__ pe_b2)
{
    __shared__ int   sel[NK];
    __shared__ float gx[NK][3];
    __shared__ float hbuf[NK][64];
    __shared__ float s_v[8]; __shared__ int s_i[8];
    int g = blockIdx.x, tid = threadIdx.x;
    int b = g >> 9;
    const float* X = xyz + (size_t)b*3*NPTS;
    const float* c = g_newxyz + (size_t)g*3;
    float cx=c[0], cy=c[1], cz=c[2];
    float cn2 = __fadd_rn(__fadd_rn(__fmul_rn(cx,cx),__fmul_rn(cy,cy)),__fmul_rn(cz,cz));
    float v[32];
    float bv=3.4e38f; int bi=0x7fffffff;
#pragma unroll
    for (int j=0;j<32;j++){
        int i = tid + j*256;
        float x=X[i], y=X[NPTS+i], z=X[2*NPTS+i];
        float pn2 = __fadd_rn(__fadd_rn(__fmul_rn(x,x),__fmul_rn(y,y)),__fmul_rn(z,z));
        float dot = __fadd_rn(__fadd_rn(__fmul_rn(cx,x),__fmul_rn(cy,y)),__fmul_rn(cz,z));
        float d = __fadd_rn(__fadd_rn(cn2,pn2), __fmul_rn(-2.0f,dot));
        v[j] = d;
        if (d < bv){ bv=d; bi=i; }
    }
    unsigned removed = 0u;
    int lane=tid&31, warp=tid>>5;
    for (int r=0;r<NK;r++){
        float wv=bv; int wi=bi;
#pragma unroll
        for (int off=16; off; off>>=1){
            float ov=__shfl_down_sync(0xffffffffu,wv,off);
            int   oi=__shfl_down_sync(0xffffffffu,wi,off);
            if (ov<wv || (ov==wv && oi<wi)){wv=ov;wi=oi;}
        }
        if (lane==0){ s_v[warp]=wv; s_i[warp]=wi; }
        __syncthreads();
        float gv = s_v[lane & 7]; int gi = s_i[lane & 7];
#pragma unroll
        for (int off=4; off; off>>=1){
            float ov=__shfl_xor_sync(0xffffffffu,gv,off);
            int   oi=__shfl_xor_sync(0xffffffffu,gi,off);
            if (ov<gv || (ov==gv && oi<gi)){gv=ov;gi=oi;}
        }
        if (tid==0) sel[r]=gi;
        __syncthreads();
        if ((gi & 255) == tid){
            removed |= 1u << (gi >> 8);
            bv=3.4e38f; bi=0x7fffffff;
#pragma unroll
            for (int j=0;j<32;j++){
                if (!((removed>>j)&1u) && v[j] < bv){ bv=v[j]; bi=tid+j*256; }
            }
        }
    }
    if (tid < 96){
        int k = tid/3, cc = tid - k*3;
        gx[k][cc] = X[cc*NPTS + sel[k]];
    }
    __syncthreads();
    for (int e=tid;e<NK*64;e+=256){
        int k=e>>6, cc=e&63;
        float val = pe_b1[cc] + gx[k][0]*pe_w1[cc*3] + gx[k][1]*pe_w1[cc*3+1] + gx[k][2]*pe_w1[cc*3+2];
        val = (val - bn_m[cc]) / sqrtf(bn_v[cc] + EPSV) * bn_g[cc] + bn_b[cc];
        hbuf[k][cc] = fmaxf(val, 0.0f);
    }
    __syncthreads();
    {
        int k = tid >> 3, dl = tid & 7;
        float acc[16];
#pragma unroll
        for (int jj=0;jj<16;jj++) acc[jj] = pe_b2[dl + 8*jj];
        for (int cc=0;cc<64;cc++){
            float hv = hbuf[k][cc];
            const float* w = g_pe2_t + cc*DM + dl;
#pragma unroll
            for (int jj=0;jj<16;jj++) acc[jj] += hv * __ldg(w + 8*jj);
        }
        const float* fr = g_featT + ((size_t)b*NPTS + sel[k])*DM + dl;
        float* xo = g_xbuf + ((size_t)g*NK + k)*DM + dl;
#pragma unroll
        for (int jj=0;jj<16;jj++) xo[8*jj] = fr[8*jj] + acc[jj];
    }
}

// ---------------- GEMM tile, double-buffered cp.async weight staging ----------------
template<int NJ4, int KC, bool RELU>
__device__ __forceinline__ void gemm_db(const float* src, int sld, int K,
    const float* __restrict__ Wt, const float* __restrict__ bias,
    float* ws, float* dst, int dld, int warp, int lane, int tid)
{
    const int M = 128*NJ4;
    const int CH = KC*M;       // floats per buffer
    const int NOP = CH/4;      // 16B cp.async ops per chunk
    const int nch = K/KC;
    const float* s0 = src + warp*4*sld;
    unsigned long long acc[4][2*NJ4];
#pragma unroll
    for (int i=0;i<4;i++)
#pragma unroll
        for (int j=0;j<2*NJ4;j++) acc[i][j]=0ull;

    {   // prologue: stage chunk 0 into buffer 0
        const float4* gs = (const float4*)Wt;
        float4* sd = (float4*)ws;
#pragma unroll
        for (int i=tid;i<NOP;i+=256) cpasync16(sd+i, gs+i);
        CPASYNC_COMMIT;
    }
    CPASYNC_WAIT0;
    __syncthreads();

    for (int c=0;c<nch;c++){
        if (c+1 < nch){   // prefetch next chunk into the other buffer
            const float4* gs = (const float4*)(Wt + (size_t)(c+1)*CH);
            float4* sd = (float4*)(ws + ((c+1)&1)*CH);
#pragma unroll
            for (int i=tid;i<NOP;i+=256) cpasync16(sd+i, gs+i);
            CPASYNC_COMMIT;
        }
        const float* cur = ws + (c&1)*CH;
        const int k0 = c*KC;
#pragma unroll
        for (int kk4=0; kk4<KC/4; kk4++){
            float xa0[4], xa1[4], xa2[4], xa3[4];
            *(float4*)xa0 = *(const float4*)(s0 +           k0 + kk4*4);
            *(float4*)xa1 = *(const float4*)(s0 +   sld +   k0 + kk4*4);
            *(float4*)xa2 = *(const float4*)(s0 + 2*sld +   k0 + kk4*4);
            *(float4*)xa3 = *(const float4*)(s0 + 3*sld +   k0 + kk4*4);
#pragma unroll
            for (int q=0;q<4;q++){
                unsigned long long X0=pk2(xa0[q]), X1=pk2(xa1[q]), X2=pk2(xa2[q]), X3=pk2(xa3[q]);
                const ulonglong2* w = (const ulonglong2*)(cur + (kk4*4+q)*M) + lane;
#pragma unroll
                for (int j=0;j<NJ4;j++){
                    ulonglong2 wv = w[32*j];
                    acc[0][2*j]   = fma2(X0, wv.x, acc[0][2*j]);
                    acc[1][2*j]   = fma2(X1, wv.x, acc[1][2*j]);
                    acc[2][2*j]   = fma2(X2, wv.x, acc[2][2*j]);
                    acc[3][2*j]   = fma2(X3, wv.x, acc[3][2*j]);
                    acc[0][2*j+1] = fma2(X0, wv.y, acc[0][2*j+1]);
                    acc[1][2*j+1] = fma2(X1, wv.y, acc[1][2*j+1]);
                    acc[2][2*j+1] = fma2(X2, wv.y, acc[2][2*j+1]);
                    acc[3][2*j+1] = fma2(X3, wv.y, acc[3][2*j+1]);
                }
            }
        }
        CPASYNC_WAIT0;
        __syncthreads();
    }
#pragma unroll
    for (int j=0;j<NJ4;j++){
        float4 bv = *(const float4*)(bias + 4*lane + 128*j);
#pragma unroll
        for (int i=0;i<4;i++){
            float2 a0 = up2(acc[i][2*j]), a1 = up2(acc[i][2*j+1]);
            float4 v;
            v.x = a0.x + bv.x; v.y = a0.y + bv.y; v.z = a1.x + bv.z; v.w = a1.y + bv.w;
            if (RELU){ v.x=fmaxf(v.x,0.f); v.y=fmaxf(v.y,0.f); v.z=fmaxf(v.z,0.f); v.w=fmaxf(v.w,0.f); }
            *(float4*)(dst + (warp*4+i)*dld + 4*lane + 128*j) = v;
        }
    }
}

__device__ __forceinline__ void add_ln(float* xs, const float* y,
    const float* __restrict__ gam, const float* __restrict__ bet, int tid)
{
    int t = tid>>3, sub = tid&7;
    float* xr = xs + t*136 + sub*16;
    const float* yr = y + t*388 + sub*16;
    float v[16]; float s=0.0f;
#pragma unroll
    for (int d=0; d<16; d++){ v[d] = xr[d] + yr[d]; s += v[d]; }
#pragma unroll
    for (int m=4;m;m>>=1) s += __shfl_xor_sync(0xffffffffu, s, m, 8);
    float mean = s * (1.0f/128.0f);
    float s2=0.0f;
#pragma unroll
    for (int d=0;d<16;d++){ float dv = v[d]-mean; s2 += dv*dv; }
#pragma unroll
    for (int m=4;m;m>>=1) s2 += __shfl_xor_sync(0xffffffffu, s2, m, 8);
    float rs = 1.0f / sqrtf(s2*(1.0f/128.0f) + EPSV);
#pragma unroll
    for (int d=0;d<16;d++){
        int dd = sub*16 + d;
        xr[d] = (v[d]-mean)*rs*gam[dd] + bet[dd];
    }
}

// smem: xs 32x136 | bf 32x388 | ws 8192 floats (double-buffered staging)
#define SMEM_FLOATS (32*136 + 32*388 + 8192)

__global__ __launch_bounds__(256,2) void k_xform(
    const float* __restrict__ bqkv, const float* __restrict__ bo,
    const float* __restrict__ l1g,  const float* __restrict__ l1b,
    const float* __restrict__ b1,   const float* __restrict__ b2,
    const float* __restrict__ l2g,  const float* __restrict__ l2b,
    const float* __restrict__ fcb)
{
    extern __shared__ float sm[];
    float* xs = sm;                    // 32 x 136
    float* bf = sm + 32*136;           // 32 x 388
    float* ws = sm + 32*136 + 32*388;  // staging (2 buffers)
    int g = blockIdx.x, tid = threadIdx.x;
    int warp = tid>>5, lane = tid&31;
    for (int e=tid;e<NK*DM;e+=256){
        int k=e>>7, d=e&127;
        xs[k*136+d] = g_xbuf[(size_t)g*NK*DM + e];
    }
    __syncthreads();
    for (int L=0;L<NLAY;L++){
        // QKV: 32x384, KC=8 (2x3072 buffers)
        gemm_db<3,8,false>(xs,136,128, g_wqkv_t + L*DM*384, bqkv + L*384, ws, bf,388, warp,lane,tid);
        __syncthreads();
        // Attention: warp = head, lane = query token
        {
            int qo = warp*HDIM, ko = 128 + warp*HDIM, vo = 256 + warp*HDIM;
            float* row = bf + lane*388;
            const ulonglong2* qr = (const ulonglong2*)(row+qo);
            ulonglong2 qa = qr[0], qb = qr[1], qc = qr[2], qd = qr[3];
            float s[32];
#pragma unroll 4
            for (int j=0;j<32;j++){
                const ulonglong2* kr = (const ulonglong2*)(bf + j*388 + ko);
                ulonglong2 ka = kr[0], kb = kr[1], kc = kr[2], kd = kr[3];
                unsigned long long p = 0ull;
                p = fma2(qa.x, ka.x, p); p = fma2(qa.y, ka.y, p);
                p = fma2(qb.x, kb.x, p); p = fma2(qb.y, kb.y, p);
                p = fma2(qc.x, kc.x, p); p = fma2(qc.y, kc.y, p);
                p = fma2(qd.x, kd.x, p); p = fma2(qd.y, kd.y, p);
                float2 pf = up2(p);
                s[j] = (pf.x + pf.y) * 0.25f;
            }
            float mx=-3.4e38f;
#pragma unroll
            for (int j=0;j<32;j++) mx = fmaxf(mx, s[j]);
            float sum=0.0f;
#pragma unroll
            for (int j=0;j<32;j++){ s[j]=__expf(s[j]-mx); sum+=s[j]; }
            float inv = 1.0f/sum;
            unsigned long long o[8];
#pragma unroll
            for (int m=0;m<8;m++) o[m]=0ull;
#pragma unroll 4
            for (int j=0;j<32;j++){
                unsigned long long P = pk2(s[j]*inv);
                const ulonglong2* vr = (const ulonglong2*)(bf + j*388 + vo);
                ulonglong2 va = vr[0], vb = vr[1], vc = vr[2], vd = vr[3];
                o[0]=fma2(P,va.x,o[0]); o[1]=fma2(P,va.y,o[1]);
                o[2]=fma2(P,vb.x,o[2]); o[3]=fma2(P,vb.y,o[3]);
                o[4]=fma2(P,vc.x,o[4]); o[5]=fma2(P,vc.y,o[5]);
                o[6]=fma2(P,vd.x,o[6]); o[7]=fma2(P,vd.y,o[7]);
            }
            ulonglong2* orow = (ulonglong2*)(row+qo);
            orow[0] = make_ulonglong2(o[0],o[1]);
            orow[1] = make_ulonglong2(o[2],o[3]);
            orow[2] = make_ulonglong2(o[4],o[5]);
            orow[3] = make_ulonglong2(o[6],o[7]);
        }
        __syncthreads();
        // o @ Wo -> bf cols 256:384, KC=16 (2x2048)
        gemm_db<1,16,false>(bf,388,128, g_wo_t + L*DM*DM, bo + L*DM, ws, bf+256,388, warp,lane,tid);
        __syncthreads();
        add_ln(xs, bf+256, l1g + L*DM, l1b + L*DM, tid);
        __syncthreads();
        // FFN1: 32x256, KC=16 (2x4096)
        gemm_db<2,16,true>(xs,136,128, g_w1_t + L*DM*DFF, b1 + L*DFF, ws, bf,388, warp,lane,tid);
        __syncthreads();
        // FFN2: 32x128, K=256, KC=16 (2x2048)
        gemm_db<1,16,false>(bf,388,256, g_w2_t + L*DFF*DM, b2 + L*DM, ws, bf+256,388, warp,lane,tid);
        __syncthreads();
        add_ln(xs, bf+256, l2g + L*DM, l2b + L*DM, tid);
        __syncthreads();
    }
    // max pool over tokens
    if (tid < DM){
        float m = -3.4e38f;
#pragma unroll
        for (int t=0;t<NK;t++) m = fmaxf(m, xs[t*136+tid]);
        bf[tid] = m;
    }
    __syncthreads();
    // FC: 256 outputs
    {
        int o = tid;
        float acc = fcb[o];
#pragma unroll 4
        for (int k=0;k<DM;k++) acc += bf[k]*__ldg(g_fc_t + k*DOUT + o);
        int b = g>>9, s = g & 511;
        g_fcout[((size_t)b*DOUT + o)*NS + s] = acc;
    }
}

// ---------------- linear upsample [B,O,S] -> [B,O,N] ----------------
__global__ void k_interp(float* __restrict__ out){
    int i = blockIdx.x*256 + threadIdx.x;
    if (i >= NBATCH*DOUT*NPTS) return;
    int n = i & (NPTS-1);
    int rest = i >> 13;   // b*256 + o
    float pos = (float)n * (511.0f/8191.0f);
    float fi = floorf(pos);
    int i0 = (int)fi;
    int i1 = min(i0+1, NS-1);
    float w = pos - fi;
    const float* row = g_fcout + (size_t)rest*NS;
    out[NBATCH*3*NS + i] = row[i0]*(1.0f-w) + row[i1]*w;
}

// ---------------- launch ----------------
extern "C" void kernel_launch(void* const* d_in, const int* in_sizes, int n_in,
                              void* d_out, int out_size)
{
    (void)in_sizes; (void)n_in; (void)out_size;
    const float* xyz   = (const float*)d_in[0];
    const float* feat  = (const float*)d_in[1];
    const float* pe_w1 = (const float*)d_in[2];
    const float* pe_b1 = (const float*)d_in[3];
    const float* bn_g  = (const float*)d_in[4];
    const float* bn_b  = (const float*)d_in[5];
    const float* bn_m  = (const float*)d_in[6];
    const float* bn_v  = (const float*)d_in[7];
    const float* pe_w2 = (const float*)d_in[8];
    const float* pe_b2 = (const float*)d_in[9];
    const float* wqkv  = (const float*)d_in[10];
    const float* bqkv  = (const float*)d_in[11];
    const float* wo    = (const float*)d_in[12];
    const float* bo    = (const float*)d_in[13];
    const float* l1g   = (const float*)d_in[14];
    const float* l1b   = (const float*)d_in[15];
    const float* w1    = (const float*)d_in[16];
    const float* b1    = (const float*)d_in[17];
    const float* w2    = (const float*)d_in[18];
    const float* b2    = (const float*)d_in[19];
    const float* l2g   = (const float*)d_in[20];
    const float* l2b   = (const float*)d_in[21];
    const float* fcw   = (const float*)d_in[22];
    const float* fcb   = (const float*)d_in[23];
    float* out = (float*)d_out;

    k_prep<<<8704,256>>>(feat, wqkv, wo, w1, w2, fcw, pe_w2);        // 1
    k_fps<<<NBATCH,512>>>(xyz, out);                                 // 2
    k_knn_pe<<<NGROUP,256>>>(xyz, pe_w1, pe_b1, bn_g, bn_b, bn_m, bn_v, pe_b2); // 3
    cudaFuncSetAttribute(k_xform, cudaFuncAttributeMaxDynamicSharedMemorySize, SMEM_FLOATS*4);
    k_xform<<<NGROUP,256,SMEM_FLOATS*4>>>(bqkv,bo,l1g,l1b,b1,b2,l2g,l2b,fcb);   // 4 <- profiled slot
    k_interp<<<(NBATCH*DOUT*NPTS)/256,256>>>(out);                   // 5
}